// round 2
// baseline (speedup 1.0000x reference)
#include <cuda_runtime.h>
#include <math.h>

// Problem constants
#define BSZ   2
#define SEQ   2048
#define EMB   2048
#define NH    16
#define DH    128
#define QKVN  ((NH + 2) * DH)   // 2304

// Scratch (allocation-free rule: __device__ globals)
__device__ float g_qkv[(size_t)BSZ * SEQ * QKVN];    // [B*S, 2304]
__device__ float g_attn[(size_t)BSZ * SEQ * EMB];    // [B*S, 2048]

// ---------------------------------------------------------------------------
// Generic fp32 GEMM: C[M,N] = A[M,K] @ B[K,N], all row-major.
// 128x128 block, KTILE=8, 256 threads, 8x8 per-thread fragments.
// B-fragment split into cols [tx*4, tx*4+4) and [64+tx*4, 64+tx*4+4) so the
// LDS.128 fragment loads are bank-conflict free.
// Requires M,N,K multiples of 128/8 (true for all three uses).
// ---------------------------------------------------------------------------
__global__ void __launch_bounds__(256) gemm128(const float* __restrict__ A,
                                               const float* __restrict__ Bm,
                                               float* __restrict__ C,
                                               int M, int N, int K) {
    __shared__ float As[8][132];   // [kk][m], padded: conflict-free transpose stores
    __shared__ float Bs[8][128];   // [kk][n]

    const int t  = threadIdx.x;
    const int bm = blockIdx.y * 128;
    const int bn = blockIdx.x * 128;
    const int ty = t >> 4;         // 0..15 -> rows ty*8..+8
    const int tx = t & 15;         // 0..15 -> cols tx*4 and 64+tx*4

    const int arow = t >> 1;            // 0..127
    const int ak   = (t & 1) << 2;      // 0 or 4
    const int brow = t >> 5;            // 0..7
    const int bcol = (t & 31) << 2;     // 0..124

    const float* Ap = A + (size_t)(bm + arow) * K + ak;
    const float* Bp = Bm + (size_t)brow * N + bn + bcol;

    float acc[8][8];
#pragma unroll
    for (int i = 0; i < 8; i++)
#pragma unroll
        for (int j = 0; j < 8; j++) acc[i][j] = 0.0f;

    for (int k0 = 0; k0 < K; k0 += 8) {
        // prefetch into registers before the barrier (overlaps prior compute)
        float4 av = *(const float4*)(Ap + k0);
        float4 bv = *(const float4*)(Bp + (size_t)k0 * N);
        __syncthreads();
        As[ak + 0][arow] = av.x;
        As[ak + 1][arow] = av.y;
        As[ak + 2][arow] = av.z;
        As[ak + 3][arow] = av.w;
        *(float4*)&Bs[brow][bcol] = bv;
        __syncthreads();

#pragma unroll
        for (int kk = 0; kk < 8; kk++) {
            float4 a0 = *(const float4*)&As[kk][ty * 8];
            float4 a1 = *(const float4*)&As[kk][ty * 8 + 4];
            float4 b0 = *(const float4*)&Bs[kk][tx * 4];
            float4 b1 = *(const float4*)&Bs[kk][64 + tx * 4];
            float a[8] = {a0.x, a0.y, a0.z, a0.w, a1.x, a1.y, a1.z, a1.w};
            float b[8] = {b0.x, b0.y, b0.z, b0.w, b1.x, b1.y, b1.z, b1.w};
#pragma unroll
            for (int i = 0; i < 8; i++)
#pragma unroll
                for (int j = 0; j < 8; j++) acc[i][j] += a[i] * b[j];
        }
    }

#pragma unroll
    for (int i = 0; i < 8; i++) {
        float* Cr = C + (size_t)(bm + ty * 8 + i) * N + bn;
        float4 c0 = make_float4(acc[i][0], acc[i][1], acc[i][2], acc[i][3]);
        float4 c1 = make_float4(acc[i][4], acc[i][5], acc[i][6], acc[i][7]);
        *(float4*)(Cr + tx * 4)      = c0;
        *(float4*)(Cr + 64 + tx * 4) = c1;
    }
}

// ---------------------------------------------------------------------------
// Flash-attention MQA kernel.
// Grid: (S/64, H, B). Block: 256 threads as 16x16.
// Each block: 64 queries of head h, streams over all 2048 keys in 64-wide tiles.
// Thread (ty,tx): score frag 4 queries (ty*4..) x 4 keys (tx*4..),
//                 O frag 4 queries x 8 cols (tx*4.. and 64+tx*4..).
// K tile is XOR-swizzled by ((row>>2)&7)<<2 so fragment reads (rows stride
// 4*128 words across lanes) are conflict-free.
// ---------------------------------------------------------------------------
__global__ void __launch_bounds__(256) mqa_flash(const float* __restrict__ qkv,
                                                 float* __restrict__ attn) {
    extern __shared__ float sm[];
    float* Qs = sm;                 // [64][128], pre-scaled by 1/sqrt(D)
    float* Ks = sm + 64 * 128;      // [64][128], swizzled
    float* Vs = sm + 2 * 64 * 128;  // [64][128]
    float* Ps = sm + 3 * 64 * 128;  // [64][64]

    const int t  = threadIdx.x;
    const int ty = t >> 4, tx = t & 15;
    const int q0 = blockIdx.x * 64;
    const int h  = blockIdx.y;
    const int b  = blockIdx.z;
    const int qy = ty * 4;
    const int kx = tx * 4;
    const float scale = rsqrtf((float)DH);

    // tile-load mapping: 8 float4 per thread; row = c*8 + t/32, d4 = (t%32)*4
    const int lrow = t >> 5;
    const int ld4  = (t & 31) << 2;

    // ---- load Q tile (once), fold in softmax scale ----
#pragma unroll
    for (int c = 0; c < 8; c++) {
        int row = c * 8 + lrow;
        float4 v = *(const float4*)(qkv + (size_t)(b * SEQ + q0 + row) * QKVN + h * DH + ld4);
        v.x *= scale; v.y *= scale; v.z *= scale; v.w *= scale;
        *(float4*)&Qs[row * 128 + ld4] = v;
    }

    float m_[4], l_[4], O[4][8];
#pragma unroll
    for (int i = 0; i < 4; i++) {
        m_[i] = -1e30f; l_[i] = 0.0f;
#pragma unroll
        for (int j = 0; j < 8; j++) O[i][j] = 0.0f;
    }

    const int swz = (tx & 7) << 2;   // matches store swizzle for rows kx..kx+3

    for (int t0 = 0; t0 < SEQ; t0 += 64) {
        __syncthreads();   // previous tile's PV reads done
        // ---- load K,V tiles (MQA: shared across heads; L2-resident) ----
#pragma unroll
        for (int c = 0; c < 8; c++) {
            int row = c * 8 + lrow;
            const float* base = qkv + (size_t)(b * SEQ + t0 + row) * QKVN;
            float4 kv = *(const float4*)(base + EMB + ld4);
            float4 vv = *(const float4*)(base + EMB + DH + ld4);
            int ks = ((row >> 2) & 7) << 2;
            *(float4*)&Ks[row * 128 + (ld4 ^ ks)] = kv;
            *(float4*)&Vs[row * 128 + ld4]        = vv;
        }
        __syncthreads();

        // ---- scores: s[i][j] = Q[qy+i] . K[kx+j]  (scale folded into Q) ----
        float s[4][4];
#pragma unroll
        for (int i = 0; i < 4; i++)
#pragma unroll
            for (int j = 0; j < 4; j++) s[i][j] = 0.0f;

#pragma unroll 8
        for (int d = 0; d < 128; d += 4) {
            float4 qv[4], kv[4];
#pragma unroll
            for (int i = 0; i < 4; i++)
                qv[i] = *(const float4*)&Qs[(qy + i) * 128 + d];
#pragma unroll
            for (int j = 0; j < 4; j++)
                kv[j] = *(const float4*)&Ks[(kx + j) * 128 + (d ^ swz)];
#pragma unroll
            for (int i = 0; i < 4; i++)
#pragma unroll
                for (int j = 0; j < 4; j++)
                    s[i][j] += qv[i].x * kv[j].x + qv[i].y * kv[j].y +
                               qv[i].z * kv[j].z + qv[i].w * kv[j].w;
        }

        // ---- streaming softmax update (row reduce across 16 tx lanes) ----
#pragma unroll
        for (int i = 0; i < 4; i++) {
            float mt = fmaxf(fmaxf(s[i][0], s[i][1]), fmaxf(s[i][2], s[i][3]));
#pragma unroll
            for (int off = 8; off > 0; off >>= 1)
                mt = fmaxf(mt, __shfl_xor_sync(0xffffffffu, mt, off, 16));
            float mn = fmaxf(m_[i], mt);
            float corr = __expf(m_[i] - mn);
            float4 p;
            p.x = __expf(s[i][0] - mn);
            p.y = __expf(s[i][1] - mn);
            p.z = __expf(s[i][2] - mn);
            p.w = __expf(s[i][3] - mn);
            float rs = p.x + p.y + p.z + p.w;
#pragma unroll
            for (int off = 8; off > 0; off >>= 1)
                rs += __shfl_xor_sync(0xffffffffu, rs, off, 16);
            l_[i] = l_[i] * corr + rs;
            m_[i] = mn;
#pragma unroll
            for (int j = 0; j < 8; j++) O[i][j] *= corr;
            *(float4*)&Ps[(qy + i) * 64 + kx] = p;
        }
        __syncthreads();

        // ---- O += P @ V ----
#pragma unroll 4
        for (int kk = 0; kk < 64; kk += 4) {
            float parr[4][4];
#pragma unroll
            for (int i = 0; i < 4; i++) {
                float4 pv = *(const float4*)&Ps[(qy + i) * 64 + kk];
                parr[i][0] = pv.x; parr[i][1] = pv.y;
                parr[i][2] = pv.z; parr[i][3] = pv.w;
            }
#pragma unroll
            for (int u = 0; u < 4; u++) {
                float4 v1 = *(const float4*)&Vs[(kk + u) * 128 + tx * 4];
                float4 v2 = *(const float4*)&Vs[(kk + u) * 128 + 64 + tx * 4];
#pragma unroll
                for (int i = 0; i < 4; i++) {
                    float pu = parr[i][u];
                    O[i][0] += pu * v1.x; O[i][1] += pu * v1.y;
                    O[i][2] += pu * v1.z; O[i][3] += pu * v1.w;
                    O[i][4] += pu * v2.x; O[i][5] += pu * v2.y;
                    O[i][6] += pu * v2.z; O[i][7] += pu * v2.w;
                }
            }
        }
    }

    // ---- epilogue: normalize, write attn[b, q, h*128 + c] ----
#pragma unroll
    for (int i = 0; i < 4; i++) {
        float inv = 1.0f / l_[i];
        float* Ar = attn + (size_t)(b * SEQ + q0 + qy + i) * EMB + h * DH;
        float4 o0 = make_float4(O[i][0] * inv, O[i][1] * inv, O[i][2] * inv, O[i][3] * inv);
        float4 o1 = make_float4(O[i][4] * inv, O[i][5] * inv, O[i][6] * inv, O[i][7] * inv);
        *(float4*)(Ar + tx * 4)      = o0;
        *(float4*)(Ar + 64 + tx * 4) = o1;
    }
}

// ---------------------------------------------------------------------------
extern "C" void kernel_launch(void* const* d_in, const int* in_sizes, int n_in,
                              void* d_out, int out_size) {
    const float* x      = (const float*)d_in[0];   // [B,S,E]
    const float* w_attn = (const float*)d_in[1];   // [E, 2304]
    const float* w_out  = (const float*)d_in[2];   // [E, E]
    float* out = (float*)d_out;                    // [B,S,E]

    float* qkv  = nullptr;
    float* attn = nullptr;
    cudaGetSymbolAddress((void**)&qkv,  g_qkv);
    cudaGetSymbolAddress((void**)&attn, g_attn);

    const int flash_smem = (3 * 64 * 128 + 64 * 64) * (int)sizeof(float);  // 112 KB
    cudaFuncSetAttribute(mqa_flash, cudaFuncAttributeMaxDynamicSharedMemorySize,
                         flash_smem);

    dim3 blk(256);
    const int M = BSZ * SEQ;  // 4096

    // 1) qkv = x @ w_attn   : [4096,2048]x[2048,2304]
    gemm128<<<dim3(QKVN / 128, M / 128), blk>>>(x, w_attn, qkv, M, QKVN, EMB);

    // 2) flash MQA attention -> g_attn [B,S,E]
    mqa_flash<<<dim3(SEQ / 64, NH, BSZ), blk, flash_smem>>>(qkv, attn);

    // 3) out = attn @ w_out : [4096,2048]x[2048,2048]
    gemm128<<<dim3(EMB / 128, M / 128), blk>>>(attn, w_out, out, M, EMB, EMB);
}

// round 4
// speedup vs baseline: 1.3243x; 1.3243x over previous
#include <cuda_runtime.h>
#include <cuda_bf16.h>
#include <math.h>
#include <stdint.h>

#define BSZ   2
#define SEQ   2048
#define EMB   2048
#define NH    16
#define DH    128
#define QKVN  ((NH + 2) * DH)   // 2304
#define MROWS (BSZ * SEQ)       // 4096
#define GK    2048               // inner K of both GEMMs

// ---------------- scratch (__device__ globals: allocation-free) ------------
__device__ __align__(128) __nv_bfloat16 g_xhi[(size_t)MROWS * EMB];
__device__ __align__(128) __nv_bfloat16 g_xlo[(size_t)MROWS * EMB];
__device__ __align__(128) __nv_bfloat16 g_wahi[(size_t)QKVN * EMB];
__device__ __align__(128) __nv_bfloat16 g_walo[(size_t)QKVN * EMB];
__device__ __align__(128) __nv_bfloat16 g_wohi[(size_t)EMB * EMB];
__device__ __align__(128) __nv_bfloat16 g_wolo[(size_t)EMB * EMB];
__device__ __align__(128) float         g_qkv[(size_t)MROWS * QKVN];
__device__ __align__(128) __nv_bfloat16 g_ahi[(size_t)MROWS * EMB];
__device__ __align__(128) __nv_bfloat16 g_alo[(size_t)MROWS * EMB];

// ---------------- PTX helpers (sm_80-class only: no 'a' features) ----------
__device__ __forceinline__ uint32_t smem_u32(const void* p) {
    uint32_t a;
    asm("{ .reg .u64 t; cvta.to.shared.u64 t, %1; cvt.u32.u64 %0, t; }"
        : "=r"(a) : "l"(p));
    return a;
}
__device__ __forceinline__ void cp_async16(uint32_t dst, const void* src) {
    asm volatile("cp.async.cg.shared.global [%0], [%1], 16;"
                 :: "r"(dst), "l"(src) : "memory");
}
__device__ __forceinline__ void cp_commit() {
    asm volatile("cp.async.commit_group;" ::: "memory");
}
__device__ __forceinline__ void cp_wait1() {
    asm volatile("cp.async.wait_group 1;" ::: "memory");
}
__device__ __forceinline__ void cp_wait0() {
    asm volatile("cp.async.wait_group 0;" ::: "memory");
}
__device__ __forceinline__ void ldsm4(uint32_t* r, uint32_t addr) {
    asm volatile("ldmatrix.sync.aligned.m8n8.x4.shared.b16 {%0,%1,%2,%3}, [%4];"
                 : "=r"(r[0]), "=r"(r[1]), "=r"(r[2]), "=r"(r[3]) : "r"(addr));
}
__device__ __forceinline__ void ldsm2(uint32_t* r, uint32_t addr) {
    asm volatile("ldmatrix.sync.aligned.m8n8.x2.shared.b16 {%0,%1}, [%2];"
                 : "=r"(r[0]), "=r"(r[1]) : "r"(addr));
}
__device__ __forceinline__ void mma16816(float* c, const uint32_t* a,
                                         const uint32_t* b) {
    asm volatile(
        "mma.sync.aligned.m16n8k16.row.col.f32.bf16.bf16.f32 "
        "{%0,%1,%2,%3}, {%4,%5,%6,%7}, {%8,%9}, {%0,%1,%2,%3};"
        : "+f"(c[0]), "+f"(c[1]), "+f"(c[2]), "+f"(c[3])
        : "r"(a[0]), "r"(a[1]), "r"(a[2]), "r"(a[3]), "r"(b[0]), "r"(b[1]));
}

// ---------------------------------------------------------------------------
// split fp32 -> (hi, lo) bf16 elementwise
// ---------------------------------------------------------------------------
__global__ void __launch_bounds__(256) split_f32(const float* __restrict__ src,
                                                 __nv_bfloat16* __restrict__ hi,
                                                 __nv_bfloat16* __restrict__ lo,
                                                 int n4) {
    int i = blockIdx.x * blockDim.x + threadIdx.x;
    int stride = gridDim.x * blockDim.x;
    for (; i < n4; i += stride) {
        float4 v = ((const float4*)src)[i];
        __nv_bfloat16 h0 = __float2bfloat16(v.x), h1 = __float2bfloat16(v.y);
        __nv_bfloat16 h2 = __float2bfloat16(v.z), h3 = __float2bfloat16(v.w);
        __nv_bfloat16 l0 = __float2bfloat16(v.x - __bfloat162float(h0));
        __nv_bfloat16 l1 = __float2bfloat16(v.y - __bfloat162float(h1));
        __nv_bfloat16 l2 = __float2bfloat16(v.z - __bfloat162float(h2));
        __nv_bfloat16 l3 = __float2bfloat16(v.w - __bfloat162float(h3));
        ((__nv_bfloat162*)hi)[2 * i]     = __nv_bfloat162(h0, h1);
        ((__nv_bfloat162*)hi)[2 * i + 1] = __nv_bfloat162(h2, h3);
        ((__nv_bfloat162*)lo)[2 * i]     = __nv_bfloat162(l0, l1);
        ((__nv_bfloat162*)lo)[2 * i + 1] = __nv_bfloat162(l2, l3);
    }
}

// ---------------------------------------------------------------------------
// transpose + split: src [R][C] fp32 -> hi/lo [C][R] bf16
// ---------------------------------------------------------------------------
__global__ void __launch_bounds__(256) transpose_split(const float* __restrict__ src,
                                                       __nv_bfloat16* __restrict__ hi,
                                                       __nv_bfloat16* __restrict__ lo,
                                                       int R, int C) {
    __shared__ float t[32][33];
    int c0 = blockIdx.x * 32, r0 = blockIdx.y * 32;
    int tx = threadIdx.x & 31, ty = threadIdx.x >> 5;  // 32 x 8
#pragma unroll
    for (int i = 0; i < 32; i += 8)
        t[ty + i][tx] = src[(size_t)(r0 + ty + i) * C + c0 + tx];
    __syncthreads();
#pragma unroll
    for (int i = 0; i < 32; i += 8) {
        float v = t[tx][ty + i];
        __nv_bfloat16 h = __float2bfloat16(v);
        __nv_bfloat16 l = __float2bfloat16(v - __bfloat162float(h));
        size_t o = (size_t)(c0 + ty + i) * R + r0 + tx;
        hi[o] = h;
        lo[o] = l;
    }
}

// ---------------------------------------------------------------------------
// Split-bf16 GEMM via mma.sync (HMMA): C[M,N] = (Ahi+Alo) @ (Bhi+Blo)^T
// A: [M][K] row-major bf16 (hi/lo), B: [N][K] row-major bf16 (hi/lo = W^T).
// CTA tile 128x128, 8 warps each 64x32, K chunk 32, cp.async double buffer.
// smem tile rows padded to 80B -> ldmatrix conflict-free.
// ---------------------------------------------------------------------------
#define KCH     32
#define ROWB    80                     // 64B data + 16B pad
#define TILEB   (128 * ROWB)           // 10240 B
#define STAGEB  (4 * TILEB)            // Ahi Alo Bhi Blo = 40960 B
#define GSMEM   (2 * STAGEB)           // 81920 B

__global__ void __launch_bounds__(256)
gemm_mma(const __nv_bfloat16* __restrict__ Ahi, const __nv_bfloat16* __restrict__ Alo,
         const __nv_bfloat16* __restrict__ Bhi, const __nv_bfloat16* __restrict__ Blo,
         float* __restrict__ C, int N) {
    extern __shared__ char smc[];
    const uint32_t sbase = smem_u32(smc);

    const int tid  = threadIdx.x;
    const int wid  = tid >> 5;
    const int lane = tid & 31;
    const int bm = blockIdx.y * 128;
    const int bn = blockIdx.x * 128;
    const int wm = (wid >> 2) * 64;    // warp row offset in tile
    const int wn = (wid & 3) * 32;     // warp col offset in tile

    // loader mapping: row r = tid>>1 (0..127), half = tid&1 -> 32B
    const int r    = tid >> 1;
    const int half = tid & 1;
    const __nv_bfloat16* srcs[4] = {
        Ahi + (size_t)(bm + r) * GK, Alo + (size_t)(bm + r) * GK,
        Bhi + (size_t)(bn + r) * GK, Blo + (size_t)(bn + r) * GK};
    const uint32_t dst_row = (uint32_t)(r * ROWB + half * 32);

    float c[4][4][4];
#pragma unroll
    for (int mt = 0; mt < 4; mt++)
#pragma unroll
        for (int nt = 0; nt < 4; nt++)
#pragma unroll
            for (int k = 0; k < 4; k++) c[mt][nt][k] = 0.0f;

    const int NCH = GK / KCH;   // 64

    // prologue: chunk 0 -> stage 0
#pragma unroll
    for (int tI = 0; tI < 4; tI++) {
        uint32_t d = sbase + tI * TILEB + dst_row;
        const __nv_bfloat16* s = srcs[tI] + half * 16;
        cp_async16(d, s);
        cp_async16(d + 16, s + 8);
    }
    cp_commit();

    for (int ch = 0; ch < NCH; ch++) {
        const uint32_t st = sbase + (ch & 1) * STAGEB;
        if (ch + 1 < NCH) {
            const uint32_t st2 = sbase + ((ch + 1) & 1) * STAGEB;
            const int k0 = (ch + 1) * KCH;
#pragma unroll
            for (int tI = 0; tI < 4; tI++) {
                uint32_t d = st2 + tI * TILEB + dst_row;
                const __nv_bfloat16* s = srcs[tI] + k0 + half * 16;
                cp_async16(d, s);
                cp_async16(d + 16, s + 8);
            }
            cp_commit();
            cp_wait1();
        } else {
            cp_wait0();
        }
        __syncthreads();

        // compute on stage st: 2 k16 steps
#pragma unroll
        for (int ks = 0; ks < 2; ks++) {
            uint32_t ah[4][4], al[4][4], bh[4][2], bl[4][2];
#pragma unroll
            for (int mt = 0; mt < 4; mt++) {
                uint32_t ra = st + (uint32_t)((wm + mt * 16 + (lane & 15)) * ROWB +
                                              ks * 32 + (lane >> 4) * 16);
                ldsm4(ah[mt], ra);
                ldsm4(al[mt], ra + TILEB);
            }
#pragma unroll
            for (int nt = 0; nt < 4; nt++) {
                uint32_t rb = st + 2 * TILEB +
                              (uint32_t)((wn + nt * 8 + (lane & 7)) * ROWB +
                                         ks * 32 + ((lane >> 3) & 1) * 16);
                ldsm2(bh[nt], rb);
                ldsm2(bl[nt], rb + TILEB);
            }
#pragma unroll
            for (int mt = 0; mt < 4; mt++)
#pragma unroll
                for (int nt = 0; nt < 4; nt++) {
                    mma16816(c[mt][nt], ah[mt], bh[nt]);
                    mma16816(c[mt][nt], ah[mt], bl[nt]);
                    mma16816(c[mt][nt], al[mt], bh[nt]);
                }
        }
        __syncthreads();   // stage consumed; safe to overwrite next iter
    }

    // epilogue
#pragma unroll
    for (int mt = 0; mt < 4; mt++)
#pragma unroll
        for (int nt = 0; nt < 4; nt++) {
            int row = bm + wm + mt * 16 + (lane >> 2);
            int col = bn + wn + nt * 8 + (lane & 3) * 2;
            *(float2*)&C[(size_t)row * N + col] =
                make_float2(c[mt][nt][0], c[mt][nt][1]);
            *(float2*)&C[(size_t)(row + 8) * N + col] =
                make_float2(c[mt][nt][2], c[mt][nt][3]);
        }
}

// ---------------------------------------------------------------------------
// Flash-attention MQA (fp32 SIMT), epilogue emits split-bf16 directly.
// ---------------------------------------------------------------------------
__global__ void __launch_bounds__(256) mqa_flash(const float* __restrict__ qkv,
                                                 __nv_bfloat16* __restrict__ ahi,
                                                 __nv_bfloat16* __restrict__ alo) {
    extern __shared__ float smf[];
    float* Qs = smf;
    float* Ks = smf + 64 * 128;
    float* Vs = smf + 2 * 64 * 128;
    float* Ps = smf + 3 * 64 * 128;

    const int t  = threadIdx.x;
    const int ty = t >> 4, tx = t & 15;
    const int q0 = blockIdx.x * 64;
    const int h  = blockIdx.y;
    const int b  = blockIdx.z;
    const int qy = ty * 4;
    const int kx = tx * 4;
    const float scale = rsqrtf((float)DH);

    const int lrow = t >> 5;
    const int ld4  = (t & 31) << 2;

#pragma unroll
    for (int c = 0; c < 8; c++) {
        int row = c * 8 + lrow;
        float4 v = *(const float4*)(qkv + (size_t)(b * SEQ + q0 + row) * QKVN + h * DH + ld4);
        v.x *= scale; v.y *= scale; v.z *= scale; v.w *= scale;
        *(float4*)&Qs[row * 128 + ld4] = v;
    }

    float m_[4], l_[4], O[4][8];
#pragma unroll
    for (int i = 0; i < 4; i++) {
        m_[i] = -1e30f; l_[i] = 0.0f;
#pragma unroll
        for (int j = 0; j < 8; j++) O[i][j] = 0.0f;
    }

    const int swz = (tx & 7) << 2;

    for (int t0 = 0; t0 < SEQ; t0 += 64) {
        __syncthreads();
#pragma unroll
        for (int c = 0; c < 8; c++) {
            int row = c * 8 + lrow;
            const float* base = qkv + (size_t)(b * SEQ + t0 + row) * QKVN;
            float4 kv = *(const float4*)(base + EMB + ld4);
            float4 vv = *(const float4*)(base + EMB + DH + ld4);
            int ks = ((row >> 2) & 7) << 2;
            *(float4*)&Ks[row * 128 + (ld4 ^ ks)] = kv;
            *(float4*)&Vs[row * 128 + ld4]        = vv;
        }
        __syncthreads();

        float s[4][4];
#pragma unroll
        for (int i = 0; i < 4; i++)
#pragma unroll
            for (int j = 0; j < 4; j++) s[i][j] = 0.0f;

#pragma unroll 8
        for (int d = 0; d < 128; d += 4) {
            float4 qv[4], kv[4];
#pragma unroll
            for (int i = 0; i < 4; i++)
                qv[i] = *(const float4*)&Qs[(qy + i) * 128 + d];
#pragma unroll
            for (int j = 0; j < 4; j++)
                kv[j] = *(const float4*)&Ks[(kx + j) * 128 + (d ^ swz)];
#pragma unroll
            for (int i = 0; i < 4; i++)
#pragma unroll
                for (int j = 0; j < 4; j++)
                    s[i][j] += qv[i].x * kv[j].x + qv[i].y * kv[j].y +
                               qv[i].z * kv[j].z + qv[i].w * kv[j].w;
        }

#pragma unroll
        for (int i = 0; i < 4; i++) {
            float mt = fmaxf(fmaxf(s[i][0], s[i][1]), fmaxf(s[i][2], s[i][3]));
#pragma unroll
            for (int off = 8; off > 0; off >>= 1)
                mt = fmaxf(mt, __shfl_xor_sync(0xffffffffu, mt, off, 16));
            float mn = fmaxf(m_[i], mt);
            float corr = __expf(m_[i] - mn);
            float4 p;
            p.x = __expf(s[i][0] - mn);
            p.y = __expf(s[i][1] - mn);
            p.z = __expf(s[i][2] - mn);
            p.w = __expf(s[i][3] - mn);
            float rs = p.x + p.y + p.z + p.w;
#pragma unroll
            for (int off = 8; off > 0; off >>= 1)
                rs += __shfl_xor_sync(0xffffffffu, rs, off, 16);
            l_[i] = l_[i] * corr + rs;
            m_[i] = mn;
#pragma unroll
            for (int j = 0; j < 8; j++) O[i][j] *= corr;
            *(float4*)&Ps[(qy + i) * 64 + kx] = p;
        }
        __syncthreads();

#pragma unroll 4
        for (int kk = 0; kk < 64; kk += 4) {
            float parr[4][4];
#pragma unroll
            for (int i = 0; i < 4; i++) {
                float4 pv = *(const float4*)&Ps[(qy + i) * 64 + kk];
                parr[i][0] = pv.x; parr[i][1] = pv.y;
                parr[i][2] = pv.z; parr[i][3] = pv.w;
            }
#pragma unroll
            for (int u = 0; u < 4; u++) {
                float4 v1 = *(const float4*)&Vs[(kk + u) * 128 + tx * 4];
                float4 v2 = *(const float4*)&Vs[(kk + u) * 128 + 64 + tx * 4];
#pragma unroll
                for (int i = 0; i < 4; i++) {
                    float pu = parr[i][u];
                    O[i][0] += pu * v1.x; O[i][1] += pu * v1.y;
                    O[i][2] += pu * v1.z; O[i][3] += pu * v1.w;
                    O[i][4] += pu * v2.x; O[i][5] += pu * v2.y;
                    O[i][6] += pu * v2.z; O[i][7] += pu * v2.w;
                }
            }
        }
    }

    // epilogue: normalize, split to bf16 hi/lo
#pragma unroll
    for (int i = 0; i < 4; i++) {
        float inv = 1.0f / l_[i];
        size_t rowo = (size_t)(b * SEQ + q0 + qy + i) * EMB + h * DH;
#pragma unroll
        for (int g = 0; g < 2; g++) {
            int colb = (g == 0) ? tx * 4 : 64 + tx * 4;
            float v0 = O[i][g * 4 + 0] * inv, v1 = O[i][g * 4 + 1] * inv;
            float v2 = O[i][g * 4 + 2] * inv, v3 = O[i][g * 4 + 3] * inv;
            __nv_bfloat16 h0 = __float2bfloat16(v0), h1 = __float2bfloat16(v1);
            __nv_bfloat16 h2 = __float2bfloat16(v2), h3 = __float2bfloat16(v3);
            __nv_bfloat16 l0 = __float2bfloat16(v0 - __bfloat162float(h0));
            __nv_bfloat16 l1 = __float2bfloat16(v1 - __bfloat162float(h1));
            __nv_bfloat16 l2 = __float2bfloat16(v2 - __bfloat162float(h2));
            __nv_bfloat16 l3 = __float2bfloat16(v3 - __bfloat162float(h3));
            *(__nv_bfloat162*)(ahi + rowo + colb)     = __nv_bfloat162(h0, h1);
            *(__nv_bfloat162*)(ahi + rowo + colb + 2) = __nv_bfloat162(h2, h3);
            *(__nv_bfloat162*)(alo + rowo + colb)     = __nv_bfloat162(l0, l1);
            *(__nv_bfloat162*)(alo + rowo + colb + 2) = __nv_bfloat162(l2, l3);
        }
    }
}

// ---------------------------------------------------------------------------
extern "C" void kernel_launch(void* const* d_in, const int* in_sizes, int n_in,
                              void* d_out, int out_size) {
    const float* x      = (const float*)d_in[0];   // [B,S,E]
    const float* w_attn = (const float*)d_in[1];   // [E, 2304]
    const float* w_out  = (const float*)d_in[2];   // [E, E]
    float* out = (float*)d_out;

    __nv_bfloat16 *xhi, *xlo, *wahi, *walo, *wohi, *wolo, *ahi, *alo;
    float* qkv;
    cudaGetSymbolAddress((void**)&xhi, g_xhi);
    cudaGetSymbolAddress((void**)&xlo, g_xlo);
    cudaGetSymbolAddress((void**)&wahi, g_wahi);
    cudaGetSymbolAddress((void**)&walo, g_walo);
    cudaGetSymbolAddress((void**)&wohi, g_wohi);
    cudaGetSymbolAddress((void**)&wolo, g_wolo);
    cudaGetSymbolAddress((void**)&ahi, g_ahi);
    cudaGetSymbolAddress((void**)&alo, g_alo);
    cudaGetSymbolAddress((void**)&qkv, g_qkv);

    const int flash_smem = (3 * 64 * 128 + 64 * 64) * (int)sizeof(float);
    cudaFuncSetAttribute(mqa_flash, cudaFuncAttributeMaxDynamicSharedMemorySize,
                         flash_smem);
    cudaFuncSetAttribute(gemm_mma, cudaFuncAttributeMaxDynamicSharedMemorySize,
                         GSMEM);

    // 1) convert inputs
    split_f32<<<512, 256>>>(x, xhi, xlo, MROWS * EMB / 4);
    transpose_split<<<dim3(QKVN / 32, EMB / 32), 256>>>(w_attn, wahi, walo, EMB, QKVN);
    transpose_split<<<dim3(EMB / 32, EMB / 32), 256>>>(w_out, wohi, wolo, EMB, EMB);

    // 2) qkv = x @ w_attn  (HMMA tensor cores, split-bf16 3-pass)
    gemm_mma<<<dim3(QKVN / 128, MROWS / 128), 256, GSMEM>>>(
        xhi, xlo, wahi, walo, qkv, QKVN);

    // 3) flash MQA -> split-bf16 attn
    mqa_flash<<<dim3(SEQ / 64, NH, BSZ), 256, flash_smem>>>(qkv, ahi, alo);

    // 4) out = attn @ w_out  (HMMA tensor cores, split-bf16 3-pass)
    gemm_mma<<<dim3(EMB / 128, MROWS / 128), 256, GSMEM>>>(
        ahi, alo, wohi, wolo, out, EMB);
}

// round 5
// speedup vs baseline: 2.1161x; 1.5979x over previous
#include <cuda_runtime.h>
#include <cuda_bf16.h>
#include <cuda_fp16.h>
#include <math.h>
#include <stdint.h>

#define BSZ   2
#define SEQ   2048
#define EMB   2048
#define NH    16
#define DH    128
#define QKVN  ((NH + 2) * DH)   // 2304
#define MROWS (BSZ * SEQ)       // 4096
#define GK    2048               // inner K of both GEMMs

// ---------------- scratch (__device__ globals: allocation-free) ------------
__device__ __align__(128) __nv_bfloat16 g_xhi[(size_t)MROWS * EMB];
__device__ __align__(128) __nv_bfloat16 g_xlo[(size_t)MROWS * EMB];
__device__ __align__(128) __nv_bfloat16 g_wahi[(size_t)QKVN * EMB];
__device__ __align__(128) __nv_bfloat16 g_walo[(size_t)QKVN * EMB];
__device__ __align__(128) __nv_bfloat16 g_wohi[(size_t)EMB * EMB];
__device__ __align__(128) __nv_bfloat16 g_wolo[(size_t)EMB * EMB];
__device__ __align__(128) float         g_qkv[(size_t)MROWS * QKVN];
__device__ __align__(128) __nv_bfloat16 g_ahi[(size_t)MROWS * EMB];
__device__ __align__(128) __nv_bfloat16 g_alo[(size_t)MROWS * EMB];

// ---------------- PTX helpers (sm_80-class only; no 'a' features) ----------
__device__ __forceinline__ uint32_t smem_u32(const void* p) {
    uint32_t a;
    asm("{ .reg .u64 t; cvta.to.shared.u64 t, %1; cvt.u32.u64 %0, t; }"
        : "=r"(a) : "l"(p));
    return a;
}
__device__ __forceinline__ void cp_async16(uint32_t dst, const void* src) {
    asm volatile("cp.async.cg.shared.global [%0], [%1], 16;"
                 :: "r"(dst), "l"(src) : "memory");
}
__device__ __forceinline__ void cp_commit() {
    asm volatile("cp.async.commit_group;" ::: "memory");
}
__device__ __forceinline__ void cp_wait1() {
    asm volatile("cp.async.wait_group 1;" ::: "memory");
}
__device__ __forceinline__ void cp_wait0() {
    asm volatile("cp.async.wait_group 0;" ::: "memory");
}
__device__ __forceinline__ void ldsm4(uint32_t* r, uint32_t addr) {
    asm volatile("ldmatrix.sync.aligned.m8n8.x4.shared.b16 {%0,%1,%2,%3}, [%4];"
                 : "=r"(r[0]), "=r"(r[1]), "=r"(r[2]), "=r"(r[3]) : "r"(addr));
}
__device__ __forceinline__ void ldsm2(uint32_t* r, uint32_t addr) {
    asm volatile("ldmatrix.sync.aligned.m8n8.x2.shared.b16 {%0,%1}, [%2];"
                 : "=r"(r[0]), "=r"(r[1]) : "r"(addr));
}
__device__ __forceinline__ void ldsm4t(uint32_t* r, uint32_t addr) {
    asm volatile("ldmatrix.sync.aligned.m8n8.x4.trans.shared.b16 {%0,%1,%2,%3}, [%4];"
                 : "=r"(r[0]), "=r"(r[1]), "=r"(r[2]), "=r"(r[3]) : "r"(addr));
}
__device__ __forceinline__ void ldsm2t(uint32_t* r, uint32_t addr) {
    asm volatile("ldmatrix.sync.aligned.m8n8.x2.trans.shared.b16 {%0,%1}, [%2];"
                 : "=r"(r[0]), "=r"(r[1]) : "r"(addr));
}
__device__ __forceinline__ void mma16816(float* c, const uint32_t* a,
                                         const uint32_t* b) {
    asm volatile(
        "mma.sync.aligned.m16n8k16.row.col.f32.bf16.bf16.f32 "
        "{%0,%1,%2,%3}, {%4,%5,%6,%7}, {%8,%9}, {%0,%1,%2,%3};"
        : "+f"(c[0]), "+f"(c[1]), "+f"(c[2]), "+f"(c[3])
        : "r"(a[0]), "r"(a[1]), "r"(a[2]), "r"(a[3]), "r"(b[0]), "r"(b[1]));
}
__device__ __forceinline__ void mma_bf16(float* c, const uint32_t* a,
                                         uint32_t b0, uint32_t b1) {
    asm volatile(
        "mma.sync.aligned.m16n8k16.row.col.f32.bf16.bf16.f32 "
        "{%0,%1,%2,%3}, {%4,%5,%6,%7}, {%8,%9}, {%0,%1,%2,%3};"
        : "+f"(c[0]), "+f"(c[1]), "+f"(c[2]), "+f"(c[3])
        : "r"(a[0]), "r"(a[1]), "r"(a[2]), "r"(a[3]), "r"(b0), "r"(b1));
}
__device__ __forceinline__ void mma_f16(float* c, uint32_t a0, uint32_t a1,
                                        uint32_t a2, uint32_t a3,
                                        uint32_t b0, uint32_t b1) {
    asm volatile(
        "mma.sync.aligned.m16n8k16.row.col.f32.f16.f16.f32 "
        "{%0,%1,%2,%3}, {%4,%5,%6,%7}, {%8,%9}, {%0,%1,%2,%3};"
        : "+f"(c[0]), "+f"(c[1]), "+f"(c[2]), "+f"(c[3])
        : "r"(a0), "r"(a1), "r"(a2), "r"(a3), "r"(b0), "r"(b1));
}
// exp2 of two f32 via one f16x2 MUFU: returns half2 {lo=2^xlo, hi=2^xhi}
__device__ __forceinline__ uint32_t ex2_f16x2(float xhi, float xlo) {
    uint32_t h, r;
    asm("cvt.rn.f16x2.f32 %0, %1, %2;" : "=r"(h) : "f"(xhi), "f"(xlo));
    asm("ex2.approx.f16x2 %0, %1;" : "=r"(r) : "r"(h));
    return r;
}
__device__ __forceinline__ uint32_t pbf2(float x, float y) {
    __nv_bfloat162 t(__float2bfloat16(x), __float2bfloat16(y));
    return *(uint32_t*)&t;
}
__device__ __forceinline__ uint32_t phf2(float x, float y) {
    __half2 t(__float2half_rn(x), __float2half_rn(y));
    return *(uint32_t*)&t;
}

// ---------------------------------------------------------------------------
// split fp32 -> (hi, lo) bf16 elementwise
// ---------------------------------------------------------------------------
__global__ void __launch_bounds__(256) split_f32(const float* __restrict__ src,
                                                 __nv_bfloat16* __restrict__ hi,
                                                 __nv_bfloat16* __restrict__ lo,
                                                 int n4) {
    int i = blockIdx.x * blockDim.x + threadIdx.x;
    int stride = gridDim.x * blockDim.x;
    for (; i < n4; i += stride) {
        float4 v = ((const float4*)src)[i];
        __nv_bfloat16 h0 = __float2bfloat16(v.x), h1 = __float2bfloat16(v.y);
        __nv_bfloat16 h2 = __float2bfloat16(v.z), h3 = __float2bfloat16(v.w);
        __nv_bfloat16 l0 = __float2bfloat16(v.x - __bfloat162float(h0));
        __nv_bfloat16 l1 = __float2bfloat16(v.y - __bfloat162float(h1));
        __nv_bfloat16 l2 = __float2bfloat16(v.z - __bfloat162float(h2));
        __nv_bfloat16 l3 = __float2bfloat16(v.w - __bfloat162float(h3));
        ((__nv_bfloat162*)hi)[2 * i]     = __nv_bfloat162(h0, h1);
        ((__nv_bfloat162*)hi)[2 * i + 1] = __nv_bfloat162(h2, h3);
        ((__nv_bfloat162*)lo)[2 * i]     = __nv_bfloat162(l0, l1);
        ((__nv_bfloat162*)lo)[2 * i + 1] = __nv_bfloat162(l2, l3);
    }
}

// ---------------------------------------------------------------------------
// transpose + split: src [R][C] fp32 -> hi/lo [C][R] bf16
// ---------------------------------------------------------------------------
__global__ void __launch_bounds__(256) transpose_split(const float* __restrict__ src,
                                                       __nv_bfloat16* __restrict__ hi,
                                                       __nv_bfloat16* __restrict__ lo,
                                                       int R, int C) {
    __shared__ float t[32][33];
    int c0 = blockIdx.x * 32, r0 = blockIdx.y * 32;
    int tx = threadIdx.x & 31, ty = threadIdx.x >> 5;  // 32 x 8
#pragma unroll
    for (int i = 0; i < 32; i += 8)
        t[ty + i][tx] = src[(size_t)(r0 + ty + i) * C + c0 + tx];
    __syncthreads();
#pragma unroll
    for (int i = 0; i < 32; i += 8) {
        float v = t[tx][ty + i];
        __nv_bfloat16 h = __float2bfloat16(v);
        __nv_bfloat16 l = __float2bfloat16(v - __bfloat162float(h));
        size_t o = (size_t)(c0 + ty + i) * R + r0 + tx;
        hi[o] = h;
        lo[o] = l;
    }
}

// ---------------------------------------------------------------------------
// Split-bf16 GEMM via mma.sync (HMMA): C[M,N] = (Ahi+Alo) @ (Bhi+Blo)^T
// ---------------------------------------------------------------------------
#define KCH     32
#define ROWB    80
#define TILEB   (128 * ROWB)
#define STAGEB  (4 * TILEB)
#define GSMEM   (2 * STAGEB)

__global__ void __launch_bounds__(256)
gemm_mma(const __nv_bfloat16* __restrict__ Ahi, const __nv_bfloat16* __restrict__ Alo,
         const __nv_bfloat16* __restrict__ Bhi, const __nv_bfloat16* __restrict__ Blo,
         float* __restrict__ C, int N) {
    extern __shared__ char smc[];
    const uint32_t sbase = smem_u32(smc);

    const int tid  = threadIdx.x;
    const int wid  = tid >> 5;
    const int lane = tid & 31;
    const int bm = blockIdx.y * 128;
    const int bn = blockIdx.x * 128;
    const int wm = (wid >> 2) * 64;
    const int wn = (wid & 3) * 32;

    const int r    = tid >> 1;
    const int half = tid & 1;
    const __nv_bfloat16* srcs[4] = {
        Ahi + (size_t)(bm + r) * GK, Alo + (size_t)(bm + r) * GK,
        Bhi + (size_t)(bn + r) * GK, Blo + (size_t)(bn + r) * GK};
    const uint32_t dst_row = (uint32_t)(r * ROWB + half * 32);

    float c[4][4][4];
#pragma unroll
    for (int mt = 0; mt < 4; mt++)
#pragma unroll
        for (int nt = 0; nt < 4; nt++)
#pragma unroll
            for (int k = 0; k < 4; k++) c[mt][nt][k] = 0.0f;

    const int NCH = GK / KCH;

#pragma unroll
    for (int tI = 0; tI < 4; tI++) {
        uint32_t d = sbase + tI * TILEB + dst_row;
        const __nv_bfloat16* s = srcs[tI] + half * 16;
        cp_async16(d, s);
        cp_async16(d + 16, s + 8);
    }
    cp_commit();

    for (int ch = 0; ch < NCH; ch++) {
        const uint32_t st = sbase + (ch & 1) * STAGEB;
        if (ch + 1 < NCH) {
            const uint32_t st2 = sbase + ((ch + 1) & 1) * STAGEB;
            const int k0 = (ch + 1) * KCH;
#pragma unroll
            for (int tI = 0; tI < 4; tI++) {
                uint32_t d = st2 + tI * TILEB + dst_row;
                const __nv_bfloat16* s = srcs[tI] + k0 + half * 16;
                cp_async16(d, s);
                cp_async16(d + 16, s + 8);
            }
            cp_commit();
            cp_wait1();
        } else {
            cp_wait0();
        }
        __syncthreads();

#pragma unroll
        for (int ks = 0; ks < 2; ks++) {
            uint32_t ah[4][4], al[4][4], bh[4][2], bl[4][2];
#pragma unroll
            for (int mt = 0; mt < 4; mt++) {
                uint32_t ra = st + (uint32_t)((wm + mt * 16 + (lane & 15)) * ROWB +
                                              ks * 32 + (lane >> 4) * 16);
                ldsm4(ah[mt], ra);
                ldsm4(al[mt], ra + TILEB);
            }
#pragma unroll
            for (int nt = 0; nt < 4; nt++) {
                uint32_t rb = st + 2 * TILEB +
                              (uint32_t)((wn + nt * 8 + (lane & 7)) * ROWB +
                                         ks * 32 + ((lane >> 3) & 1) * 16);
                ldsm2(bh[nt], rb);
                ldsm2(bl[nt], rb + TILEB);
            }
#pragma unroll
            for (int mt = 0; mt < 4; mt++)
#pragma unroll
                for (int nt = 0; nt < 4; nt++) {
                    mma16816(c[mt][nt], ah[mt], bh[nt]);
                    mma16816(c[mt][nt], ah[mt], bl[nt]);
                    mma16816(c[mt][nt], al[mt], bh[nt]);
                }
        }
        __syncthreads();
    }

#pragma unroll
    for (int mt = 0; mt < 4; mt++)
#pragma unroll
        for (int nt = 0; nt < 4; nt++) {
            int row = bm + wm + mt * 16 + (lane >> 2);
            int col = bn + wn + nt * 8 + (lane & 3) * 2;
            *(float2*)&C[(size_t)row * N + col] =
                make_float2(c[mt][nt][0], c[mt][nt][1]);
            *(float2*)&C[(size_t)(row + 8) * N + col] =
                make_float2(c[mt][nt][2], c[mt][nt][3]);
        }
}

// ---------------------------------------------------------------------------
// Tensor-core flash MQA.
// Block: 128 queries x head h. 8 warps, each m16. K-tiles of 64 keys.
// QK^T: split-bf16 3-pass (scores log2-domain, scale*log2e folded into Q).
// softmax: ex2.approx.f16x2 (2 exps/MUFU), online max in fp32.
// PV: P f16 (direct reg reuse from QK accum) x V split-f16 2-pass.
// Row sum l = tensor-core ones-column (V col 128).
// smem rows 272B (conflict-free ldmatrix: stride = 68 words = 4 banks).
// ---------------------------------------------------------------------------
#define FROW   272
#define OFF_QHI 0
#define OFF_QLO (128 * FROW)
#define OFF_KHI (2 * 128 * FROW)
#define OFF_KLO (OFF_KHI + 64 * FROW)
#define OFF_VHI (OFF_KLO + 64 * FROW)
#define OFF_VLO (OFF_VHI + 64 * FROW)
#define FSMEM   (OFF_VLO + 64 * FROW)   // 139264 B

__global__ void __launch_bounds__(256, 1)
mqa_flash_mma(const float* __restrict__ qkv,
              __nv_bfloat16* __restrict__ ahi, __nv_bfloat16* __restrict__ alo) {
    extern __shared__ char smf[];
    const uint32_t sb = smem_u32(smf);
    const int tid  = threadIdx.x;
    const int wid  = tid >> 5;
    const int lane = tid & 31;
    const int q0 = blockIdx.x * 128;
    const int h  = blockIdx.y;
    const int b  = blockIdx.z;
    const int wm = wid * 16;

    // ---- load Q tile -> split-bf16 smem, scale*log2e folded ----
    {
        const float sc = rsqrtf((float)DH) * 1.4426950408889634f;
        int row = tid >> 1, c0 = (tid & 1) * 64;
        const float* src = qkv + (size_t)(b * SEQ + q0 + row) * QKVN + h * DH + c0;
        char* dhi = smf + OFF_QHI + row * FROW + c0 * 2;
        char* dlo = smf + OFF_QLO + row * FROW + c0 * 2;
#pragma unroll
        for (int p = 0; p < 8; p++) {
            float4 a = *(const float4*)(src + p * 8);
            float4 d = *(const float4*)(src + p * 8 + 4);
            float v[8] = {a.x * sc, a.y * sc, a.z * sc, a.w * sc,
                          d.x * sc, d.y * sc, d.z * sc, d.w * sc};
            float hv[8];
            uint4 hh, ll;
            uint32_t* hp = (uint32_t*)&hh;
            uint32_t* lp = (uint32_t*)&ll;
#pragma unroll
            for (int j = 0; j < 8; j++)
                hv[j] = __bfloat162float(__float2bfloat16(v[j]));
#pragma unroll
            for (int j = 0; j < 4; j++) {
                hp[j] = pbf2(v[2 * j], v[2 * j + 1]);
                lp[j] = pbf2(v[2 * j] - hv[2 * j], v[2 * j + 1] - hv[2 * j + 1]);
            }
            *(uint4*)(dhi + p * 16) = hh;
            *(uint4*)(dlo + p * 16) = ll;
        }
    }
    // ---- ones column for row-sum (V cols 128..135), written once ----
    if (tid < 64) {
        uint4 one = make_uint4(0x00003C00u, 0u, 0u, 0u);   // half 1.0 in col 128
        uint4 zer = make_uint4(0u, 0u, 0u, 0u);
        *(uint4*)(smf + OFF_VHI + tid * FROW + 256) = one;
        *(uint4*)(smf + OFF_VLO + tid * FROW + 256) = zer;
    }

    // ---- prefetch K/V tile 0 ----
    const int krow = tid >> 2, kcg = (tid & 3) * 32;
    float4 kr[8], vr[8];
    {
        const float* kp = qkv + (size_t)(b * SEQ + krow) * QKVN + EMB + kcg;
#pragma unroll
        for (int i = 0; i < 8; i++) {
            kr[i] = *(const float4*)(kp + i * 4);
            vr[i] = *(const float4*)(kp + 128 + i * 4);
        }
    }

    float O[17][4];
#pragma unroll
    for (int f = 0; f < 17; f++)
#pragma unroll
        for (int j = 0; j < 4; j++) O[f][j] = 0.0f;
    float m0 = -1e30f, m1 = -1e30f;

    for (int t0 = 0; t0 < SEQ; t0 += 64) {
        __syncthreads();   // smem K/V free
        // ---- convert prefetched K/V -> smem (K bf16 hi/lo, V f16 hi/lo) ----
        {
            char* kh = smf + OFF_KHI + krow * FROW + kcg * 2;
            char* kl = smf + OFF_KLO + krow * FROW + kcg * 2;
            char* vh = smf + OFF_VHI + krow * FROW + kcg * 2;
            char* vl = smf + OFF_VLO + krow * FROW + kcg * 2;
#pragma unroll
            for (int p = 0; p < 4; p++) {
                float kv[8] = {kr[2 * p].x, kr[2 * p].y, kr[2 * p].z, kr[2 * p].w,
                               kr[2 * p + 1].x, kr[2 * p + 1].y, kr[2 * p + 1].z,
                               kr[2 * p + 1].w};
                float vv[8] = {vr[2 * p].x, vr[2 * p].y, vr[2 * p].z, vr[2 * p].w,
                               vr[2 * p + 1].x, vr[2 * p + 1].y, vr[2 * p + 1].z,
                               vr[2 * p + 1].w};
                uint4 khh, kll, vhh, vll;
                uint32_t* a0 = (uint32_t*)&khh;
                uint32_t* a1 = (uint32_t*)&kll;
                uint32_t* a2 = (uint32_t*)&vhh;
                uint32_t* a3 = (uint32_t*)&vll;
#pragma unroll
                for (int j = 0; j < 4; j++) {
                    float x = kv[2 * j], y = kv[2 * j + 1];
                    float xh = __bfloat162float(__float2bfloat16(x));
                    float yh = __bfloat162float(__float2bfloat16(y));
                    a0[j] = pbf2(x, y);
                    a1[j] = pbf2(x - xh, y - yh);
                    float u = vv[2 * j], w = vv[2 * j + 1];
                    float uh = __half2float(__float2half_rn(u));
                    float wh = __half2float(__float2half_rn(w));
                    a2[j] = phf2(u, w);
                    a3[j] = phf2(u - uh, w - wh);
                }
                *(uint4*)(kh + p * 16) = khh;
                *(uint4*)(kl + p * 16) = kll;
                *(uint4*)(vh + p * 16) = vhh;
                *(uint4*)(vl + p * 16) = vll;
            }
        }
        __syncthreads();
        // ---- prefetch next tile ----
        if (t0 + 64 < SEQ) {
            const float* kp = qkv + (size_t)(b * SEQ + t0 + 64 + krow) * QKVN + EMB + kcg;
#pragma unroll
            for (int i = 0; i < 8; i++) {
                kr[i] = *(const float4*)(kp + i * 4);
                vr[i] = *(const float4*)(kp + 128 + i * 4);
            }
        }

        // ---- QK^T: split-bf16 3-pass -> scores (log2 domain) ----
        float c[8][4];
#pragma unroll
        for (int nt = 0; nt < 8; nt++)
#pragma unroll
            for (int j = 0; j < 4; j++) c[nt][j] = 0.0f;

#pragma unroll
        for (int ks = 0; ks < 8; ks++) {
            uint32_t qoff = (uint32_t)((wm + (lane & 15)) * FROW + ks * 32 +
                                       (lane >> 4) * 16);
            uint32_t ah[4], al[4];
            ldsm4(ah, sb + OFF_QHI + qoff);
            ldsm4(al, sb + OFF_QLO + qoff);
#pragma unroll
            for (int ntp = 0; ntp < 4; ntp++) {
                uint32_t koff = (uint32_t)((ntp * 16 + (lane & 15)) * FROW + ks * 32 +
                                           (lane >> 4) * 16);
                uint32_t kh[4], kl[4];
                ldsm4(kh, sb + OFF_KHI + koff);
                ldsm4(kl, sb + OFF_KLO + koff);
                mma_bf16(c[2 * ntp], ah, kh[0], kh[2]);
                mma_bf16(c[2 * ntp], ah, kl[0], kl[2]);
                mma_bf16(c[2 * ntp], al, kh[0], kh[2]);
                mma_bf16(c[2 * ntp + 1], ah, kh[1], kh[3]);
                mma_bf16(c[2 * ntp + 1], ah, kl[1], kl[3]);
                mma_bf16(c[2 * ntp + 1], al, kh[1], kh[3]);
            }
        }

        // ---- online softmax (log2 domain), p in f16x2 ----
        float mt0 = -1e30f, mt1 = -1e30f;
#pragma unroll
        for (int nt = 0; nt < 8; nt++) {
            mt0 = fmaxf(mt0, fmaxf(c[nt][0], c[nt][1]));
            mt1 = fmaxf(mt1, fmaxf(c[nt][2], c[nt][3]));
        }
        mt0 = fmaxf(mt0, __shfl_xor_sync(0xffffffffu, mt0, 1));
        mt0 = fmaxf(mt0, __shfl_xor_sync(0xffffffffu, mt0, 2));
        mt1 = fmaxf(mt1, __shfl_xor_sync(0xffffffffu, mt1, 1));
        mt1 = fmaxf(mt1, __shfl_xor_sync(0xffffffffu, mt1, 2));
        float mn0 = fmaxf(m0, mt0), mn1 = fmaxf(m1, mt1);
        float corr0 = exp2f(m0 - mn0), corr1 = exp2f(m1 - mn1);
        m0 = mn0;
        m1 = mn1;
#pragma unroll
        for (int f = 0; f < 17; f++) {
            O[f][0] *= corr0; O[f][1] *= corr0;
            O[f][2] *= corr1; O[f][3] *= corr1;
        }
        uint32_t ph[8][2];
#pragma unroll
        for (int nt = 0; nt < 8; nt++) {
            ph[nt][0] = ex2_f16x2(c[nt][1] - mn0, c[nt][0] - mn0);
            ph[nt][1] = ex2_f16x2(c[nt][3] - mn1, c[nt][2] - mn1);
        }

        // ---- PV: P f16 x V split-f16 2-pass; col 128 = row sum ----
#pragma unroll
        for (int j = 0; j < 4; j++) {
            const int kk = j * 16;
            uint32_t a0 = ph[2 * j][0], a1 = ph[2 * j][1];
            uint32_t a2 = ph[2 * j + 1][0], a3 = ph[2 * j + 1][1];
            uint32_t vrow = (uint32_t)(kk + (lane & 15)) * FROW;
#pragma unroll
            for (int np = 0; np < 8; np++) {
                uint32_t addr = sb + OFF_VHI + vrow +
                                (uint32_t)(np * 16 + (lane >> 4) * 8) * 2;
                uint32_t vh[4], vl[4];
                ldsm4t(vh, addr);
                ldsm4t(vl, addr + (OFF_VLO - OFF_VHI));
                mma_f16(O[2 * np], a0, a1, a2, a3, vh[0], vh[1]);
                mma_f16(O[2 * np], a0, a1, a2, a3, vl[0], vl[1]);
                mma_f16(O[2 * np + 1], a0, a1, a2, a3, vh[2], vh[3]);
                mma_f16(O[2 * np + 1], a0, a1, a2, a3, vl[2], vl[3]);
            }
            uint32_t lh[2];
            ldsm2t(lh, sb + OFF_VHI + vrow + 256);
            mma_f16(O[16], a0, a1, a2, a3, lh[0], lh[1]);
        }
    }

    // ---- epilogue: normalize, write split-bf16 attn ----
    float l0 = __shfl_sync(0xffffffffu, O[16][0], lane & 28);
    float l1 = __shfl_sync(0xffffffffu, O[16][2], lane & 28);
    float inv0 = 1.0f / l0, inv1 = 1.0f / l1;
    size_t base0 = (size_t)(b * SEQ + q0 + wm + (lane >> 2)) * EMB + h * DH +
                   2 * (lane & 3);
    size_t base1 = base0 + (size_t)8 * EMB;
#pragma unroll
    for (int nt = 0; nt < 16; nt++) {
        float v0 = O[nt][0] * inv0, v1 = O[nt][1] * inv0;
        float v2 = O[nt][2] * inv1, v3 = O[nt][3] * inv1;
        float h0 = __bfloat162float(__float2bfloat16(v0));
        float h1 = __bfloat162float(__float2bfloat16(v1));
        float h2 = __bfloat162float(__float2bfloat16(v2));
        float h3 = __bfloat162float(__float2bfloat16(v3));
        *(uint32_t*)(ahi + base0 + nt * 8) = pbf2(v0, v1);
        *(uint32_t*)(alo + base0 + nt * 8) = pbf2(v0 - h0, v1 - h1);
        *(uint32_t*)(ahi + base1 + nt * 8) = pbf2(v2, v3);
        *(uint32_t*)(alo + base1 + nt * 8) = pbf2(v2 - h2, v3 - h3);
    }
}

// ---------------------------------------------------------------------------
extern "C" void kernel_launch(void* const* d_in, const int* in_sizes, int n_in,
                              void* d_out, int out_size) {
    const float* x      = (const float*)d_in[0];
    const float* w_attn = (const float*)d_in[1];
    const float* w_out  = (const float*)d_in[2];
    float* out = (float*)d_out;

    __nv_bfloat16 *xhi, *xlo, *wahi, *walo, *wohi, *wolo, *ahi, *alo;
    float* qkv;
    cudaGetSymbolAddress((void**)&xhi, g_xhi);
    cudaGetSymbolAddress((void**)&xlo, g_xlo);
    cudaGetSymbolAddress((void**)&wahi, g_wahi);
    cudaGetSymbolAddress((void**)&walo, g_walo);
    cudaGetSymbolAddress((void**)&wohi, g_wohi);
    cudaGetSymbolAddress((void**)&wolo, g_wolo);
    cudaGetSymbolAddress((void**)&ahi, g_ahi);
    cudaGetSymbolAddress((void**)&alo, g_alo);
    cudaGetSymbolAddress((void**)&qkv, g_qkv);

    cudaFuncSetAttribute(gemm_mma, cudaFuncAttributeMaxDynamicSharedMemorySize,
                         GSMEM);
    cudaFuncSetAttribute(mqa_flash_mma, cudaFuncAttributeMaxDynamicSharedMemorySize,
                         FSMEM);

    // 1) convert inputs
    split_f32<<<512, 256>>>(x, xhi, xlo, MROWS * EMB / 4);
    transpose_split<<<dim3(QKVN / 32, EMB / 32), 256>>>(w_attn, wahi, walo, EMB, QKVN);
    transpose_split<<<dim3(EMB / 32, EMB / 32), 256>>>(w_out, wohi, wolo, EMB, EMB);

    // 2) qkv = x @ w_attn
    gemm_mma<<<dim3(QKVN / 128, MROWS / 128), 256, GSMEM>>>(
        xhi, xlo, wahi, walo, qkv, QKVN);

    // 3) tensor-core flash MQA -> split-bf16 attn
    mqa_flash_mma<<<dim3(SEQ / 128, NH, BSZ), 256, FSMEM>>>(qkv, ahi, alo);

    // 4) out = attn @ w_out
    gemm_mma<<<dim3(EMB / 128, MROWS / 128), 256, GSMEM>>>(
        ahi, alo, wohi, wolo, out, EMB);
}

// round 6
// speedup vs baseline: 2.2826x; 1.0786x over previous
#include <cuda_runtime.h>
#include <cuda_bf16.h>
#include <cuda_fp16.h>
#include <math.h>
#include <stdint.h>

#define BSZ   2
#define SEQ   2048
#define EMB   2048
#define NH    16
#define DH    128
#define QKVN  ((NH + 2) * DH)   // 2304
#define MROWS (BSZ * SEQ)       // 4096
#define GK    2048               // inner K of both GEMMs

// ---------------- scratch (__device__ globals: allocation-free) ------------
__device__ __align__(128) __nv_bfloat16 g_xhi[(size_t)MROWS * EMB];
__device__ __align__(128) __nv_bfloat16 g_xlo[(size_t)MROWS * EMB];
__device__ __align__(128) __nv_bfloat16 g_wahi[(size_t)QKVN * EMB];
__device__ __align__(128) __nv_bfloat16 g_walo[(size_t)QKVN * EMB];
__device__ __align__(128) __nv_bfloat16 g_wohi[(size_t)EMB * EMB];
__device__ __align__(128) __nv_bfloat16 g_wolo[(size_t)EMB * EMB];
__device__ __align__(128) float         g_qkv[(size_t)MROWS * QKVN];
__device__ __align__(128) __nv_bfloat16 g_ahi[(size_t)MROWS * EMB];
__device__ __align__(128) __nv_bfloat16 g_alo[(size_t)MROWS * EMB];
// pre-converted K/V (split)
__device__ __align__(128) __nv_bfloat16 g_khi[(size_t)MROWS * DH];
__device__ __align__(128) __nv_bfloat16 g_klo[(size_t)MROWS * DH];
__device__ __align__(128) __half        g_vhi[(size_t)MROWS * DH];
__device__ __align__(128) __half        g_vlo[(size_t)MROWS * DH];

// ---------------- PTX helpers (sm_80-class only; no 'a' features) ----------
__device__ __forceinline__ uint32_t smem_u32(const void* p) {
    uint32_t a;
    asm("{ .reg .u64 t; cvta.to.shared.u64 t, %1; cvt.u32.u64 %0, t; }"
        : "=r"(a) : "l"(p));
    return a;
}
__device__ __forceinline__ void cp_async16(uint32_t dst, const void* src) {
    asm volatile("cp.async.cg.shared.global [%0], [%1], 16;"
                 :: "r"(dst), "l"(src) : "memory");
}
__device__ __forceinline__ void cp_commit() {
    asm volatile("cp.async.commit_group;" ::: "memory");
}
__device__ __forceinline__ void cp_wait0() {
    asm volatile("cp.async.wait_group 0;" ::: "memory");
}
__device__ __forceinline__ void ldsm4(uint32_t* r, uint32_t addr) {
    asm volatile("ldmatrix.sync.aligned.m8n8.x4.shared.b16 {%0,%1,%2,%3}, [%4];"
                 : "=r"(r[0]), "=r"(r[1]), "=r"(r[2]), "=r"(r[3]) : "r"(addr));
}
__device__ __forceinline__ void ldsm4t(uint32_t* r, uint32_t addr) {
    asm volatile("ldmatrix.sync.aligned.m8n8.x4.trans.shared.b16 {%0,%1,%2,%3}, [%4];"
                 : "=r"(r[0]), "=r"(r[1]), "=r"(r[2]), "=r"(r[3]) : "r"(addr));
}
__device__ __forceinline__ void ldsm2t(uint32_t* r, uint32_t addr) {
    asm volatile("ldmatrix.sync.aligned.m8n8.x2.trans.shared.b16 {%0,%1}, [%2];"
                 : "=r"(r[0]), "=r"(r[1]) : "r"(addr));
}
__device__ __forceinline__ void mma_bf16(float* c, const uint32_t* a,
                                         uint32_t b0, uint32_t b1) {
    asm volatile(
        "mma.sync.aligned.m16n8k16.row.col.f32.bf16.bf16.f32 "
        "{%0,%1,%2,%3}, {%4,%5,%6,%7}, {%8,%9}, {%0,%1,%2,%3};"
        : "+f"(c[0]), "+f"(c[1]), "+f"(c[2]), "+f"(c[3])
        : "r"(a[0]), "r"(a[1]), "r"(a[2]), "r"(a[3]), "r"(b0), "r"(b1));
}
__device__ __forceinline__ void mma_f16(float* c, uint32_t a0, uint32_t a1,
                                        uint32_t a2, uint32_t a3,
                                        uint32_t b0, uint32_t b1) {
    asm volatile(
        "mma.sync.aligned.m16n8k16.row.col.f32.f16.f16.f32 "
        "{%0,%1,%2,%3}, {%4,%5,%6,%7}, {%8,%9}, {%0,%1,%2,%3};"
        : "+f"(c[0]), "+f"(c[1]), "+f"(c[2]), "+f"(c[3])
        : "r"(a0), "r"(a1), "r"(a2), "r"(a3), "r"(b0), "r"(b1));
}
__device__ __forceinline__ uint32_t ex2_f16x2(float xhi, float xlo) {
    uint32_t h, r;
    asm("cvt.rn.f16x2.f32 %0, %1, %2;" : "=r"(h) : "f"(xhi), "f"(xlo));
    asm("ex2.approx.f16x2 %0, %1;" : "=r"(r) : "r"(h));
    return r;
}
__device__ __forceinline__ float ex2f(float x) {
    float r;
    asm("ex2.approx.f32 %0, %1;" : "=f"(r) : "f"(x));
    return r;
}
__device__ __forceinline__ uint32_t pbf2(float x, float y) {
    __nv_bfloat162 t(__float2bfloat16(x), __float2bfloat16(y));
    return *(uint32_t*)&t;
}

// ---------------------------------------------------------------------------
// split fp32 -> (hi, lo) bf16 elementwise
// ---------------------------------------------------------------------------
__global__ void __launch_bounds__(256) split_f32(const float* __restrict__ src,
                                                 __nv_bfloat16* __restrict__ hi,
                                                 __nv_bfloat16* __restrict__ lo,
                                                 int n4) {
    int i = blockIdx.x * blockDim.x + threadIdx.x;
    int stride = gridDim.x * blockDim.x;
    for (; i < n4; i += stride) {
        float4 v = ((const float4*)src)[i];
        __nv_bfloat16 h0 = __float2bfloat16(v.x), h1 = __float2bfloat16(v.y);
        __nv_bfloat16 h2 = __float2bfloat16(v.z), h3 = __float2bfloat16(v.w);
        __nv_bfloat16 l0 = __float2bfloat16(v.x - __bfloat162float(h0));
        __nv_bfloat16 l1 = __float2bfloat16(v.y - __bfloat162float(h1));
        __nv_bfloat16 l2 = __float2bfloat16(v.z - __bfloat162float(h2));
        __nv_bfloat16 l3 = __float2bfloat16(v.w - __bfloat162float(h3));
        ((__nv_bfloat162*)hi)[2 * i]     = __nv_bfloat162(h0, h1);
        ((__nv_bfloat162*)hi)[2 * i + 1] = __nv_bfloat162(h2, h3);
        ((__nv_bfloat162*)lo)[2 * i]     = __nv_bfloat162(l0, l1);
        ((__nv_bfloat162*)lo)[2 * i + 1] = __nv_bfloat162(l2, l3);
    }
}

// ---------------------------------------------------------------------------
// transpose + split: src [R][C] fp32 -> hi/lo [C][R] bf16
// ---------------------------------------------------------------------------
__global__ void __launch_bounds__(256) transpose_split(const float* __restrict__ src,
                                                       __nv_bfloat16* __restrict__ hi,
                                                       __nv_bfloat16* __restrict__ lo,
                                                       int R, int C) {
    __shared__ float t[32][33];
    int c0 = blockIdx.x * 32, r0 = blockIdx.y * 32;
    int tx = threadIdx.x & 31, ty = threadIdx.x >> 5;
#pragma unroll
    for (int i = 0; i < 32; i += 8)
        t[ty + i][tx] = src[(size_t)(r0 + ty + i) * C + c0 + tx];
    __syncthreads();
#pragma unroll
    for (int i = 0; i < 32; i += 8) {
        float v = t[tx][ty + i];
        __nv_bfloat16 h = __float2bfloat16(v);
        __nv_bfloat16 l = __float2bfloat16(v - __bfloat162float(h));
        size_t o = (size_t)(c0 + ty + i) * R + r0 + tx;
        hi[o] = h;
        lo[o] = l;
    }
}

// ---------------------------------------------------------------------------
// one-time K/V split conversion: qkv K/V cols -> bf16 hi/lo (K), f16 hi/lo (V)
// ---------------------------------------------------------------------------
__global__ void __launch_bounds__(256) convert_kv(const float* __restrict__ qkv,
                                                  __nv_bfloat16* __restrict__ khi,
                                                  __nv_bfloat16* __restrict__ klo,
                                                  __half* __restrict__ vhi,
                                                  __half* __restrict__ vlo) {
    int row = blockIdx.x * 2 + (threadIdx.x >> 7);
    int c = threadIdx.x & 127;
    const float* src = qkv + (size_t)row * QKVN;
    float k = src[EMB + c];
    float v = src[EMB + DH + c];
    __nv_bfloat16 kh = __float2bfloat16(k);
    khi[(size_t)row * DH + c] = kh;
    klo[(size_t)row * DH + c] = __float2bfloat16(k - __bfloat162float(kh));
    __half vh = __float2half_rn(v);
    vhi[(size_t)row * DH + c] = vh;
    vlo[(size_t)row * DH + c] = __float2half_rn(v - __half2float(vh));
}

// ---------------------------------------------------------------------------
// Split-bf16 GEMM via mma.sync: C[M,N] = (Ahi+Alo) @ (Bhi+Blo)^T
// single-sync double-buffered cp.async, pass-major mma order, ldsm4 B loads.
// ---------------------------------------------------------------------------
#define KCH     32
#define ROWB    80
#define TILEB   (128 * ROWB)
#define STAGEB  (4 * TILEB)
#define GSMEM   (2 * STAGEB)

__global__ void __launch_bounds__(256)
gemm_mma(const __nv_bfloat16* __restrict__ Ahi, const __nv_bfloat16* __restrict__ Alo,
         const __nv_bfloat16* __restrict__ Bhi, const __nv_bfloat16* __restrict__ Blo,
         float* __restrict__ C, int N) {
    extern __shared__ char smc[];
    const uint32_t sbase = smem_u32(smc);

    const int tid  = threadIdx.x;
    const int wid  = tid >> 5;
    const int lane = tid & 31;
    const int bm = blockIdx.y * 128;
    const int bn = blockIdx.x * 128;
    const int wm = (wid >> 2) * 64;
    const int wn = (wid & 3) * 32;

    const int r    = tid >> 1;
    const int half = tid & 1;
    const __nv_bfloat16* srcs[4] = {
        Ahi + (size_t)(bm + r) * GK, Alo + (size_t)(bm + r) * GK,
        Bhi + (size_t)(bn + r) * GK, Blo + (size_t)(bn + r) * GK};
    const uint32_t dst_row = (uint32_t)(r * ROWB + half * 32);

    float c[4][4][4];
#pragma unroll
    for (int mt = 0; mt < 4; mt++)
#pragma unroll
        for (int nt = 0; nt < 4; nt++)
#pragma unroll
            for (int k = 0; k < 4; k++) c[mt][nt][k] = 0.0f;

    const int NCH = GK / KCH;

    // prologue: chunk 0 -> stage 0
#pragma unroll
    for (int tI = 0; tI < 4; tI++) {
        uint32_t d = sbase + tI * TILEB + dst_row;
        const __nv_bfloat16* s = srcs[tI] + half * 16;
        cp_async16(d, s);
        cp_async16(d + 16, s + 8);
    }
    cp_commit();

    for (int ch = 0; ch < NCH; ch++) {
        cp_wait0();
        __syncthreads();
        if (ch + 1 < NCH) {
            const uint32_t st2 = sbase + ((ch + 1) & 1) * STAGEB;
            const int k0 = (ch + 1) * KCH;
#pragma unroll
            for (int tI = 0; tI < 4; tI++) {
                uint32_t d = st2 + tI * TILEB + dst_row;
                const __nv_bfloat16* s = srcs[tI] + k0 + half * 16;
                cp_async16(d, s);
                cp_async16(d + 16, s + 8);
            }
            cp_commit();
        }
        const uint32_t st = sbase + (ch & 1) * STAGEB;

#pragma unroll
        for (int ks = 0; ks < 2; ks++) {
            uint32_t ah[4][4], al[4][4];
#pragma unroll
            for (int mt = 0; mt < 4; mt++) {
                uint32_t ra = st + (uint32_t)((wm + mt * 16 + (lane & 15)) * ROWB +
                                              ks * 32 + (lane >> 4) * 16);
                ldsm4(ah[mt], ra);
                ldsm4(al[mt], ra + TILEB);
            }
            uint32_t rb0 = st + 2 * TILEB +
                           (uint32_t)((wn + (lane & 15)) * ROWB + ks * 32 +
                                      (lane >> 4) * 16);
            uint32_t rb1 = rb0 + 16 * ROWB;
            uint32_t bh0[4], bh1[4], bl0[4], bl1[4];
            ldsm4(bh0, rb0);
            ldsm4(bh1, rb1);
            ldsm4(bl0, rb0 + TILEB);
            ldsm4(bl1, rb1 + TILEB);

            // pass 1: Ahi x Bhi
#pragma unroll
            for (int mt = 0; mt < 4; mt++) {
                mma_bf16(c[mt][0], ah[mt], bh0[0], bh0[2]);
                mma_bf16(c[mt][1], ah[mt], bh0[1], bh0[3]);
                mma_bf16(c[mt][2], ah[mt], bh1[0], bh1[2]);
                mma_bf16(c[mt][3], ah[mt], bh1[1], bh1[3]);
            }
            // pass 2: Ahi x Blo
#pragma unroll
            for (int mt = 0; mt < 4; mt++) {
                mma_bf16(c[mt][0], ah[mt], bl0[0], bl0[2]);
                mma_bf16(c[mt][1], ah[mt], bl0[1], bl0[3]);
                mma_bf16(c[mt][2], ah[mt], bl1[0], bl1[2]);
                mma_bf16(c[mt][3], ah[mt], bl1[1], bl1[3]);
            }
            // pass 3: Alo x Bhi
#pragma unroll
            for (int mt = 0; mt < 4; mt++) {
                mma_bf16(c[mt][0], al[mt], bh0[0], bh0[2]);
                mma_bf16(c[mt][1], al[mt], bh0[1], bh0[3]);
                mma_bf16(c[mt][2], al[mt], bh1[0], bh1[2]);
                mma_bf16(c[mt][3], al[mt], bh1[1], bh1[3]);
            }
        }
    }

#pragma unroll
    for (int mt = 0; mt < 4; mt++)
#pragma unroll
        for (int nt = 0; nt < 4; nt++) {
            int row = bm + wm + mt * 16 + (lane >> 2);
            int col = bn + wn + nt * 8 + (lane & 3) * 2;
            *(float2*)&C[(size_t)row * N + col] =
                make_float2(c[mt][nt][0], c[mt][nt][1]);
            *(float2*)&C[(size_t)(row + 8) * N + col] =
                make_float2(c[mt][nt][2], c[mt][nt][3]);
        }
}

// ---------------------------------------------------------------------------
// Tensor-core flash MQA with pre-converted K/V streamed via cp.async.
// Block: 128 queries x head. 8 warps x m16. 64-key tiles, 2 smem stages.
// ---------------------------------------------------------------------------
#define FROW    272
#define OFF_QHI 0
#define OFF_QLO (128 * FROW)
#define OFF_ST  (2 * 128 * FROW)
#define STAGEF  (4 * 64 * FROW)           // Khi Klo Vhi Vlo
#define FSMEM   (OFF_ST + 2 * STAGEF)     // 208896 B

__device__ __forceinline__ void issue_kv_tile(
    uint32_t stbase, int lr, int lcb, size_t ge,
    const __nv_bfloat16* __restrict__ khi, const __nv_bfloat16* __restrict__ klo,
    const __half* __restrict__ vhi, const __half* __restrict__ vlo) {
    uint32_t d = stbase + (uint32_t)(lr * FROW + lcb);
    const char* pk = (const char*)(khi + ge);
    const char* pK = (const char*)(klo + ge);
    const char* pv = (const char*)(vhi + ge);
    const char* pV = (const char*)(vlo + ge);
#pragma unroll
    for (int jj = 0; jj < 4; jj++) {
        cp_async16(d + jj * 16, pk + jj * 16);
        cp_async16(d + 64 * FROW + jj * 16, pK + jj * 16);
        cp_async16(d + 128 * FROW + jj * 16, pv + jj * 16);
        cp_async16(d + 192 * FROW + jj * 16, pV + jj * 16);
    }
}

__global__ void __launch_bounds__(256, 1)
mqa_flash_mma(const float* __restrict__ qkv,
              const __nv_bfloat16* __restrict__ gkhi,
              const __nv_bfloat16* __restrict__ gklo,
              const __half* __restrict__ gvhi, const __half* __restrict__ gvlo,
              __nv_bfloat16* __restrict__ ahi, __nv_bfloat16* __restrict__ alo) {
    extern __shared__ char smf[];
    const uint32_t sb = smem_u32(smf);
    const int tid  = threadIdx.x;
    const int wid  = tid >> 5;
    const int lane = tid & 31;
    const int q0 = blockIdx.x * 128;
    const int h  = blockIdx.y;
    const int b  = blockIdx.z;
    const int wm = wid * 16;

    // ---- load Q tile -> split-bf16 smem, scale*log2e folded ----
    {
        const float sc = rsqrtf((float)DH) * 1.4426950408889634f;
        int row = tid >> 1, c0 = (tid & 1) * 64;
        const float* src = qkv + (size_t)(b * SEQ + q0 + row) * QKVN + h * DH + c0;
        char* dhi = smf + OFF_QHI + row * FROW + c0 * 2;
        char* dlo = smf + OFF_QLO + row * FROW + c0 * 2;
#pragma unroll
        for (int p = 0; p < 8; p++) {
            float4 a = *(const float4*)(src + p * 8);
            float4 d = *(const float4*)(src + p * 8 + 4);
            float v[8] = {a.x * sc, a.y * sc, a.z * sc, a.w * sc,
                          d.x * sc, d.y * sc, d.z * sc, d.w * sc};
            uint4 hh, ll;
            uint32_t* hp = (uint32_t*)&hh;
            uint32_t* lp = (uint32_t*)&ll;
#pragma unroll
            for (int j = 0; j < 4; j++) {
                float x = v[2 * j], y = v[2 * j + 1];
                float xh = __bfloat162float(__float2bfloat16(x));
                float yh = __bfloat162float(__float2bfloat16(y));
                hp[j] = pbf2(x, y);
                lp[j] = pbf2(x - xh, y - yh);
            }
            *(uint4*)(dhi + p * 16) = hh;
            *(uint4*)(dlo + p * 16) = ll;
        }
    }
    // ---- ones column (V col 128) in both stages, written once ----
    if (tid < 128) {
        int s = tid >> 6, row = tid & 63;
        char* vrow = smf + OFF_ST + s * STAGEF + 128 * FROW + row * FROW + 256;
        *(uint4*)vrow = make_uint4(0x00003C00u, 0u, 0u, 0u);               // Vhi: 1.0h
        *(uint4*)(vrow + 64 * FROW) = make_uint4(0u, 0u, 0u, 0u);          // Vlo: 0
    }

    const int lr  = tid >> 2;
    const int lcb = (tid & 3) * 64;
    const size_t gebase = ((size_t)(b * SEQ + lr) << 7) + (lcb >> 1);

    float O[17][4];
#pragma unroll
    for (int f = 0; f < 17; f++)
#pragma unroll
        for (int j = 0; j < 4; j++) O[f][j] = 0.0f;
    float m0 = -1e30f, m1 = -1e30f;

    // prologue: tile 0 -> stage 0
    issue_kv_tile(sb + OFF_ST, lr, lcb, gebase, gkhi, gklo, gvhi, gvlo);
    cp_commit();

    const int NT = SEQ / 64;
    for (int t = 0; t < NT; t++) {
        cp_wait0();
        __syncthreads();
        if (t + 1 < NT) {
            issue_kv_tile(sb + OFF_ST + ((t + 1) & 1) * STAGEF, lr, lcb,
                          gebase + (size_t)(t + 1) * 64 * 128, gkhi, gklo, gvhi, gvlo);
            cp_commit();
        }
        const uint32_t stb = sb + OFF_ST + (t & 1) * STAGEF;

        // ---- QK^T: split-bf16 3-pass (log2 domain) ----
        float c[8][4];
#pragma unroll
        for (int nt = 0; nt < 8; nt++)
#pragma unroll
            for (int j = 0; j < 4; j++) c[nt][j] = 0.0f;

#pragma unroll
        for (int ks = 0; ks < 8; ks++) {
            uint32_t qoff = (uint32_t)((wm + (lane & 15)) * FROW + ks * 32 +
                                       (lane >> 4) * 16);
            uint32_t ah[4], al[4];
            ldsm4(ah, sb + OFF_QHI + qoff);
            ldsm4(al, sb + OFF_QLO + qoff);
#pragma unroll
            for (int pp = 0; pp < 2; pp++) {
                uint32_t k0 = stb + (uint32_t)((pp * 32 + (lane & 15)) * FROW +
                                               ks * 32 + (lane >> 4) * 16);
                uint32_t k1 = k0 + 16 * FROW;
                uint32_t kh0[4], kh1[4], kl0[4], kl1[4];
                ldsm4(kh0, k0);
                ldsm4(kh1, k1);
                ldsm4(kl0, k0 + 64 * FROW);
                ldsm4(kl1, k1 + 64 * FROW);
                float* c0 = c[4 * pp + 0];
                float* c1 = c[4 * pp + 1];
                float* c2 = c[4 * pp + 2];
                float* c3 = c[4 * pp + 3];
                mma_bf16(c0, ah, kh0[0], kh0[2]);
                mma_bf16(c1, ah, kh0[1], kh0[3]);
                mma_bf16(c2, ah, kh1[0], kh1[2]);
                mma_bf16(c3, ah, kh1[1], kh1[3]);
                mma_bf16(c0, ah, kl0[0], kl0[2]);
                mma_bf16(c1, ah, kl0[1], kl0[3]);
                mma_bf16(c2, ah, kl1[0], kl1[2]);
                mma_bf16(c3, ah, kl1[1], kl1[3]);
                mma_bf16(c0, al, kh0[0], kh0[2]);
                mma_bf16(c1, al, kh0[1], kh0[3]);
                mma_bf16(c2, al, kh1[0], kh1[2]);
                mma_bf16(c3, al, kh1[1], kh1[3]);
            }
        }

        // ---- online softmax (log2 domain), p in f16x2 ----
        float mt0 = -1e30f, mt1 = -1e30f;
#pragma unroll
        for (int nt = 0; nt < 8; nt++) {
            mt0 = fmaxf(mt0, fmaxf(c[nt][0], c[nt][1]));
            mt1 = fmaxf(mt1, fmaxf(c[nt][2], c[nt][3]));
        }
        mt0 = fmaxf(mt0, __shfl_xor_sync(0xffffffffu, mt0, 1));
        mt0 = fmaxf(mt0, __shfl_xor_sync(0xffffffffu, mt0, 2));
        mt1 = fmaxf(mt1, __shfl_xor_sync(0xffffffffu, mt1, 1));
        mt1 = fmaxf(mt1, __shfl_xor_sync(0xffffffffu, mt1, 2));
        float mn0 = fmaxf(m0, mt0), mn1 = fmaxf(m1, mt1);
        float corr0 = ex2f(m0 - mn0), corr1 = ex2f(m1 - mn1);
        m0 = mn0;
        m1 = mn1;
#pragma unroll
        for (int f = 0; f < 17; f++) {
            O[f][0] *= corr0; O[f][1] *= corr0;
            O[f][2] *= corr1; O[f][3] *= corr1;
        }
        uint32_t ph[8][2];
#pragma unroll
        for (int nt = 0; nt < 8; nt++) {
            ph[nt][0] = ex2_f16x2(c[nt][1] - mn0, c[nt][0] - mn0);
            ph[nt][1] = ex2_f16x2(c[nt][3] - mn1, c[nt][2] - mn1);
        }

        // ---- PV: P f16 x V split-f16 2-pass; col 128 = row sum ----
        const uint32_t vb  = stb + 128 * FROW;
#pragma unroll
        for (int j = 0; j < 4; j++) {
            uint32_t a0 = ph[2 * j][0], a1 = ph[2 * j][1];
            uint32_t a2 = ph[2 * j + 1][0], a3 = ph[2 * j + 1][1];
            uint32_t vrow = (uint32_t)((j * 16 + (lane & 15)) * FROW);
#pragma unroll
            for (int npp = 0; npp < 4; npp++) {
                uint32_t adA = vb + vrow + (uint32_t)((npp * 32 + (lane >> 4) * 8) * 2);
                uint32_t adB = adA + 32;
                uint32_t vha[4], vhb[4], vla[4], vlb[4];
                ldsm4t(vha, adA);
                ldsm4t(vhb, adB);
                ldsm4t(vla, adA + 64 * FROW);
                ldsm4t(vlb, adB + 64 * FROW);
                mma_f16(O[4 * npp + 0], a0, a1, a2, a3, vha[0], vha[1]);
                mma_f16(O[4 * npp + 1], a0, a1, a2, a3, vha[2], vha[3]);
                mma_f16(O[4 * npp + 2], a0, a1, a2, a3, vhb[0], vhb[1]);
                mma_f16(O[4 * npp + 3], a0, a1, a2, a3, vhb[2], vhb[3]);
                mma_f16(O[4 * npp + 0], a0, a1, a2, a3, vla[0], vla[1]);
                mma_f16(O[4 * npp + 1], a0, a1, a2, a3, vla[2], vla[3]);
                mma_f16(O[4 * npp + 2], a0, a1, a2, a3, vlb[0], vlb[1]);
                mma_f16(O[4 * npp + 3], a0, a1, a2, a3, vlb[2], vlb[3]);
            }
            uint32_t lh[2];
            ldsm2t(lh, vb + vrow + 256);
            mma_f16(O[16], a0, a1, a2, a3, lh[0], lh[1]);
        }
    }

    // ---- epilogue: normalize, write split-bf16 attn ----
    float l0 = __shfl_sync(0xffffffffu, O[16][0], lane & 28);
    float l1 = __shfl_sync(0xffffffffu, O[16][2], lane & 28);
    float inv0 = 1.0f / l0, inv1 = 1.0f / l1;
    size_t base0 = (size_t)(b * SEQ + q0 + wm + (lane >> 2)) * EMB + h * DH +
                   2 * (lane & 3);
    size_t base1 = base0 + (size_t)8 * EMB;
#pragma unroll
    for (int nt = 0; nt < 16; nt++) {
        float v0 = O[nt][0] * inv0, v1 = O[nt][1] * inv0;
        float v2 = O[nt][2] * inv1, v3 = O[nt][3] * inv1;
        float h0 = __bfloat162float(__float2bfloat16(v0));
        float h1 = __bfloat162float(__float2bfloat16(v1));
        float h2 = __bfloat162float(__float2bfloat16(v2));
        float h3 = __bfloat162float(__float2bfloat16(v3));
        *(uint32_t*)(ahi + base0 + nt * 8) = pbf2(v0, v1);
        *(uint32_t*)(alo + base0 + nt * 8) = pbf2(v0 - h0, v1 - h1);
        *(uint32_t*)(ahi + base1 + nt * 8) = pbf2(v2, v3);
        *(uint32_t*)(alo + base1 + nt * 8) = pbf2(v2 - h2, v3 - h3);
    }
}

// ---------------------------------------------------------------------------
extern "C" void kernel_launch(void* const* d_in, const int* in_sizes, int n_in,
                              void* d_out, int out_size) {
    const float* x      = (const float*)d_in[0];
    const float* w_attn = (const float*)d_in[1];
    const float* w_out  = (const float*)d_in[2];
    float* out = (float*)d_out;

    __nv_bfloat16 *xhi, *xlo, *wahi, *walo, *wohi, *wolo, *ahi, *alo, *khi, *klo;
    __half *vhi, *vlo;
    float* qkv;
    cudaGetSymbolAddress((void**)&xhi, g_xhi);
    cudaGetSymbolAddress((void**)&xlo, g_xlo);
    cudaGetSymbolAddress((void**)&wahi, g_wahi);
    cudaGetSymbolAddress((void**)&walo, g_walo);
    cudaGetSymbolAddress((void**)&wohi, g_wohi);
    cudaGetSymbolAddress((void**)&wolo, g_wolo);
    cudaGetSymbolAddress((void**)&ahi, g_ahi);
    cudaGetSymbolAddress((void**)&alo, g_alo);
    cudaGetSymbolAddress((void**)&khi, g_khi);
    cudaGetSymbolAddress((void**)&klo, g_klo);
    cudaGetSymbolAddress((void**)&vhi, g_vhi);
    cudaGetSymbolAddress((void**)&vlo, g_vlo);
    cudaGetSymbolAddress((void**)&qkv, g_qkv);

    cudaFuncSetAttribute(gemm_mma, cudaFuncAttributeMaxDynamicSharedMemorySize,
                         GSMEM);
    cudaFuncSetAttribute(mqa_flash_mma, cudaFuncAttributeMaxDynamicSharedMemorySize,
                         FSMEM);

    // 1) convert inputs
    split_f32<<<512, 256>>>(x, xhi, xlo, MROWS * EMB / 4);
    transpose_split<<<dim3(QKVN / 32, EMB / 32), 256>>>(w_attn, wahi, walo, EMB, QKVN);
    transpose_split<<<dim3(EMB / 32, EMB / 32), 256>>>(w_out, wohi, wolo, EMB, EMB);

    // 2) qkv = x @ w_attn
    gemm_mma<<<dim3(QKVN / 128, MROWS / 128), 256, GSMEM>>>(
        xhi, xlo, wahi, walo, qkv, QKVN);

    // 3) one-time K/V split conversion
    convert_kv<<<MROWS / 2, 256>>>(qkv, khi, klo, vhi, vlo);

    // 4) tensor-core flash MQA -> split-bf16 attn
    mqa_flash_mma<<<dim3(SEQ / 128, NH, BSZ), 256, FSMEM>>>(
        qkv, khi, klo, vhi, vlo, ahi, alo);

    // 5) out = attn @ w_out
    gemm_mma<<<dim3(EMB / 128, MROWS / 128), 256, GSMEM>>>(
        ahi, alo, wohi, wolo, out, EMB);
}